// round 9
// baseline (speedup 1.0000x reference)
#include <cuda_runtime.h>
#include <math.h>

// Problem constants (fixed by setup_inputs)
#define BSZ   2
#define LSEQ  2048
#define DM    1024
#define DI    2048          // d_inner
#define DS    16            // d_state
#define DTR   64            // dt_rank
#define NX    96            // dt_rank + 2*d_state
#define MROWS (BSZ*LSEQ)    // 4096
#define E2    (2*DI)        // 4096

// -------- scratch (device globals; no allocation allowed) --------
__device__ float g_xz  [(size_t)MROWS * E2];   // in_proj output (xi | z)
__device__ float g_xc  [(size_t)MROWS * DI];   // conv+silu output
__device__ float g_xdbl[(size_t)MROWS * NX];   // x_proj output (dt_r | B | C)
__device__ float g_dt  [(size_t)MROWS * DI];   // softplus(dt)
__device__ float g_yact[(size_t)MROWS * DI];   // scan out * silu(z)
__device__ float g_yout[(size_t)MROWS * DM];   // out_proj output

// ---------------------------------------------------------------
// Generic fp32 GEMM: C[M,N] = A[M,K] * B[N,K]^T  (both K-major)
// 64x64 tile, 256 threads, 4x4 micro-tile, K-tile 16.
// M must be a multiple of 64 (always 4096 here); N,K checked.
// EPI==1: v = softplus(v + bias[n])
// ---------------------------------------------------------------
template<int EPI>
__global__ void __launch_bounds__(256) sgemm_abt(
    const float* __restrict__ A, int lda,
    const float* __restrict__ Bm, int ldb,
    float* __restrict__ C, int ldc,
    int N, int K, const float* __restrict__ bias)
{
    __shared__ float As[16][68];   // 68 stride: keeps float4 alignment, cuts store conflicts
    __shared__ float Bs[16][68];

    const int tid = threadIdx.x;
    const int tx  = tid & 15;
    const int ty  = tid >> 4;
    const int m0  = blockIdx.y * 64;
    const int n0  = blockIdx.x * 64;

    const int lr = tid >> 2;        // 0..63 tile row for loads
    const int lk = (tid & 3) * 4;   // 0,4,8,12 k offset for loads

    float acc[4][4];
#pragma unroll
    for (int i = 0; i < 4; i++)
#pragma unroll
        for (int j = 0; j < 4; j++) acc[i][j] = 0.f;

    for (int k0 = 0; k0 < K; k0 += 16) {
        float4 av = *reinterpret_cast<const float4*>(
            A + (size_t)(m0 + lr) * lda + (k0 + lk));
        As[lk+0][lr] = av.x; As[lk+1][lr] = av.y;
        As[lk+2][lr] = av.z; As[lk+3][lr] = av.w;

        float4 bv = make_float4(0.f, 0.f, 0.f, 0.f);
        if (n0 + lr < N)
            bv = *reinterpret_cast<const float4*>(
                Bm + (size_t)(n0 + lr) * ldb + (k0 + lk));
        Bs[lk+0][lr] = bv.x; Bs[lk+1][lr] = bv.y;
        Bs[lk+2][lr] = bv.z; Bs[lk+3][lr] = bv.w;

        __syncthreads();
#pragma unroll
        for (int k = 0; k < 16; k++) {
            float4 a4 = *reinterpret_cast<const float4*>(&As[k][ty * 4]);
            float4 b4 = *reinterpret_cast<const float4*>(&Bs[k][tx * 4]);
            float a[4] = {a4.x, a4.y, a4.z, a4.w};
            float b[4] = {b4.x, b4.y, b4.z, b4.w};
#pragma unroll
            for (int i = 0; i < 4; i++)
#pragma unroll
                for (int j = 0; j < 4; j++)
                    acc[i][j] = fmaf(a[i], b[j], acc[i][j]);
        }
        __syncthreads();
    }

#pragma unroll
    for (int i = 0; i < 4; i++) {
        const int m = m0 + ty * 4 + i;
#pragma unroll
        for (int j = 0; j < 4; j++) {
            const int n = n0 + tx * 4 + j;
            if (n < N) {
                float v = acc[i][j];
                if (EPI == 1) {
                    v += bias[n];
                    v = (v > 20.f) ? v : log1pf(__expf(v));
                }
                C[(size_t)m * ldc + n] = v;
            }
        }
    }
}

// ---------------------------------------------------------------
// Causal depthwise conv (width 4) + bias + SiLU on xi half of xz
// ---------------------------------------------------------------
__global__ void __launch_bounds__(256) conv_silu_k(
    const float* __restrict__ cw, const float* __restrict__ cb)
{
    const int idx = blockIdx.x * 256 + threadIdx.x;   // over MROWS*DI
    const int d = idx & (DI - 1);
    const int m = idx >> 11;          // b*L + l
    const int l = m & (LSEQ - 1);

    float acc = cb[d];
#pragma unroll
    for (int j = 0; j < 4; j++) {
        const int ll = l - 3 + j;
        if (ll >= 0)
            acc = fmaf(cw[d * 4 + j], g_xz[(size_t)(m - 3 + j) * E2 + d], acc);
    }
    const float sg = 1.f / (1.f + __expf(-acc));
    g_xc[idx] = acc * sg;
}

// ---------------------------------------------------------------
// Selective scan. One thread per (b, d, s). 256 threads = 16 d x 16 s.
// Fused epilogue: y = (scan + D*u) * silu(z)
// ---------------------------------------------------------------
__global__ void __launch_bounds__(256) scan_k(
    const float* __restrict__ A_log, const float* __restrict__ Dp)
{
    const int s  = threadIdx.x & 15;
    const int dl = threadIdx.x >> 4;
    const int d  = blockIdx.x * 16 + dl;
    const int b  = blockIdx.y;

    const float As = -__expf(A_log[d * DS + s]);
    const float Dd = Dp[d];

    const float* dt_p = g_dt   + (size_t)b * LSEQ * DI + d;
    const float* u_p  = g_xc   + (size_t)b * LSEQ * DI + d;
    const float* bc_p = g_xdbl + (size_t)b * LSEQ * NX;
    const float* z_p  = g_xz   + (size_t)b * LSEQ * E2 + DI + d;
    float*       y_p  = g_yact + (size_t)b * LSEQ * DI + d;

    float h = 0.f;
    for (int l = 0; l < LSEQ; l++) {
        const float dt = __ldg(dt_p + (size_t)l * DI);
        const float u  = __ldg(u_p  + (size_t)l * DI);
        const float Bv = __ldg(bc_p + l * NX + DTR + s);
        const float Cv = __ldg(bc_p + l * NX + DTR + DS + s);

        const float dA = __expf(dt * As);
        h = fmaf(dA, h, dt * u * Bv);

        float y = h * Cv;
        y += __shfl_xor_sync(0xffffffffu, y, 8);
        y += __shfl_xor_sync(0xffffffffu, y, 4);
        y += __shfl_xor_sync(0xffffffffu, y, 2);
        y += __shfl_xor_sync(0xffffffffu, y, 1);

        if (s == 0) {
            const float zv = __ldg(z_p + (size_t)l * E2);
            const float sg = 1.f / (1.f + __expf(-zv));
            y_p[(size_t)l * DI] = (y + Dd * u) * (zv * sg);
        }
    }
}

// ---------------------------------------------------------------
// Residual add + LayerNorm. One block per row of 1024.
// ---------------------------------------------------------------
__global__ void __launch_bounds__(256) ln_k(
    const float* __restrict__ x,
    const float* __restrict__ g, const float* __restrict__ bb,
    float* __restrict__ out)
{
    const int r = blockIdx.x;
    const float* yp = g_yout + (size_t)r * DM;
    const float* xp = x      + (size_t)r * DM;

    float v[4];
    float sum = 0.f, sq = 0.f;
#pragma unroll
    for (int k = 0; k < 4; k++) {
        const int c = threadIdx.x + k * 256;
        const float t = yp[c] + xp[c];
        v[k] = t; sum += t; sq += t * t;
    }

    __shared__ float ssum[8], ssq[8];
#pragma unroll
    for (int o = 16; o; o >>= 1) {
        sum += __shfl_xor_sync(0xffffffffu, sum, o);
        sq  += __shfl_xor_sync(0xffffffffu, sq,  o);
    }
    const int w = threadIdx.x >> 5;
    if ((threadIdx.x & 31) == 0) { ssum[w] = sum; ssq[w] = sq; }
    __syncthreads();

    float ts = 0.f, tq = 0.f;
#pragma unroll
    for (int i = 0; i < 8; i++) { ts += ssum[i]; tq += ssq[i]; }

    const float mu  = ts * (1.f / DM);
    const float var = tq * (1.f / DM) - mu * mu;
    const float inv = rsqrtf(var + 1e-5f);

#pragma unroll
    for (int k = 0; k < 4; k++) {
        const int c = threadIdx.x + k * 256;
        out[(size_t)r * DM + c] = (v[k] - mu) * inv * g[c] + bb[c];
    }
}

// ---------------------------------------------------------------
extern "C" void kernel_launch(void* const* d_in, const int* in_sizes, int n_in,
                              void* d_out, int out_size)
{
    const float* x          = (const float*)d_in[0];
    const float* in_proj_w  = (const float*)d_in[1];
    const float* conv_w     = (const float*)d_in[2];
    const float* conv_b     = (const float*)d_in[3];
    const float* x_proj_w   = (const float*)d_in[4];
    const float* dt_proj_w  = (const float*)d_in[5];
    const float* dt_proj_b  = (const float*)d_in[6];
    const float* A_log      = (const float*)d_in[7];
    const float* Dp         = (const float*)d_in[8];
    const float* out_proj_w = (const float*)d_in[9];
    const float* ln_g       = (const float*)d_in[10];
    const float* ln_b       = (const float*)d_in[11];
    float* out = (float*)d_out;

    float *xz, *xc, *xdbl, *dt, *yact, *yout;
    cudaGetSymbolAddress((void**)&xz,   g_xz);
    cudaGetSymbolAddress((void**)&xc,   g_xc);
    cudaGetSymbolAddress((void**)&xdbl, g_xdbl);
    cudaGetSymbolAddress((void**)&dt,   g_dt);
    cudaGetSymbolAddress((void**)&yact, g_yact);
    cudaGetSymbolAddress((void**)&yout, g_yout);

    // 1) xz = x @ in_proj_w^T       (4096 x 4096 x 1024)
    sgemm_abt<0><<<dim3(E2 / 64, MROWS / 64), 256>>>(
        x, DM, in_proj_w, DM, xz, E2, E2, DM, nullptr);

    // 2) xc = silu(causal_conv(xi) + conv_b)
    conv_silu_k<<<(MROWS * DI) / 256, 256>>>(conv_w, conv_b);

    // 3) x_dbl = xc @ x_proj_w^T    (4096 x 96 x 2048)
    sgemm_abt<0><<<dim3((NX + 63) / 64, MROWS / 64), 256>>>(
        xc, DI, x_proj_w, DI, xdbl, NX, NX, DI, nullptr);

    // 4) dt = softplus(dt_r @ dt_proj_w^T + b)  (4096 x 2048 x 64)
    sgemm_abt<1><<<dim3(DI / 64, MROWS / 64), 256>>>(
        xdbl, NX, dt_proj_w, DTR, dt, DI, DI, DTR, dt_proj_b);

    // 5) selective scan + gating
    scan_k<<<dim3(DI / 16, BSZ), 256>>>(A_log, Dp);

    // 6) yout = yact @ out_proj_w^T (4096 x 1024 x 2048)
    sgemm_abt<0><<<dim3(DM / 64, MROWS / 64), 256>>>(
        yact, DI, out_proj_w, DI, yout, DM, DM, DI, nullptr);

    // 7) out = layernorm(yout + x)
    ln_k<<<MROWS, 256>>>(x, ln_g, ln_b, out);
}

// round 10
// speedup vs baseline: 1.0029x; 1.0029x over previous
#include <cuda_runtime.h>
#include <math.h>

// Problem constants (fixed by setup_inputs)
#define BSZ   2
#define LSEQ  2048
#define DM    1024
#define DI    2048          // d_inner
#define DS    16            // d_state
#define DTR   64            // dt_rank
#define NX    96            // dt_rank + 2*d_state
#define MROWS (BSZ*LSEQ)    // 4096
#define E2    (2*DI)        // 4096

// -------- scratch (device globals; no allocation allowed) --------
__device__ float g_xz  [(size_t)MROWS * E2];   // in_proj output (xi | z)
__device__ float g_xc  [(size_t)MROWS * DI];   // conv+silu output
__device__ float g_xdbl[(size_t)MROWS * NX];   // x_proj output (dt_r | B | C)
__device__ float g_dt  [(size_t)MROWS * DI];   // softplus(dt)
__device__ float g_yact[(size_t)MROWS * DI];   // scan out * silu(z)
__device__ float g_yout[(size_t)MROWS * DM];   // out_proj output

// ---------------------------------------------------------------
// Generic fp32 GEMM: C[M,N] = A[M,K] * B[N,K]^T  (both K-major)
// 64x64 tile, 256 threads, 4x4 micro-tile, K-tile 16.
// M must be a multiple of 64 (always 4096 here); N,K checked.
// EPI==1: v = softplus(v + bias[n])
// ---------------------------------------------------------------
template<int EPI>
__global__ void __launch_bounds__(256) sgemm_abt(
    const float* __restrict__ A, int lda,
    const float* __restrict__ Bm, int ldb,
    float* __restrict__ C, int ldc,
    int N, int K, const float* __restrict__ bias)
{
    __shared__ float As[16][68];   // 68 stride: keeps float4 alignment, cuts store conflicts
    __shared__ float Bs[16][68];

    const int tid = threadIdx.x;
    const int tx  = tid & 15;
    const int ty  = tid >> 4;
    const int m0  = blockIdx.y * 64;
    const int n0  = blockIdx.x * 64;

    const int lr = tid >> 2;        // 0..63 tile row for loads
    const int lk = (tid & 3) * 4;   // 0,4,8,12 k offset for loads

    float acc[4][4];
#pragma unroll
    for (int i = 0; i < 4; i++)
#pragma unroll
        for (int j = 0; j < 4; j++) acc[i][j] = 0.f;

    for (int k0 = 0; k0 < K; k0 += 16) {
        float4 av = *reinterpret_cast<const float4*>(
            A + (size_t)(m0 + lr) * lda + (k0 + lk));
        As[lk+0][lr] = av.x; As[lk+1][lr] = av.y;
        As[lk+2][lr] = av.z; As[lk+3][lr] = av.w;

        float4 bv = make_float4(0.f, 0.f, 0.f, 0.f);
        if (n0 + lr < N)
            bv = *reinterpret_cast<const float4*>(
                Bm + (size_t)(n0 + lr) * ldb + (k0 + lk));
        Bs[lk+0][lr] = bv.x; Bs[lk+1][lr] = bv.y;
        Bs[lk+2][lr] = bv.z; Bs[lk+3][lr] = bv.w;

        __syncthreads();
#pragma unroll
        for (int k = 0; k < 16; k++) {
            float4 a4 = *reinterpret_cast<const float4*>(&As[k][ty * 4]);
            float4 b4 = *reinterpret_cast<const float4*>(&Bs[k][tx * 4]);
            float a[4] = {a4.x, a4.y, a4.z, a4.w};
            float b[4] = {b4.x, b4.y, b4.z, b4.w};
#pragma unroll
            for (int i = 0; i < 4; i++)
#pragma unroll
                for (int j = 0; j < 4; j++)
                    acc[i][j] = fmaf(a[i], b[j], acc[i][j]);
        }
        __syncthreads();
    }

#pragma unroll
    for (int i = 0; i < 4; i++) {
        const int m = m0 + ty * 4 + i;
#pragma unroll
        for (int j = 0; j < 4; j++) {
            const int n = n0 + tx * 4 + j;
            if (n < N) {
                float v = acc[i][j];
                if (EPI == 1) {
                    v += bias[n];
                    v = (v > 20.f) ? v : log1pf(__expf(v));
                }
                C[(size_t)m * ldc + n] = v;
            }
        }
    }
}

// ---------------------------------------------------------------
// Causal depthwise conv (width 4) + bias + SiLU on xi half of xz
// ---------------------------------------------------------------
__global__ void __launch_bounds__(256) conv_silu_k(
    const float* __restrict__ cw, const float* __restrict__ cb)
{
    const int idx = blockIdx.x * 256 + threadIdx.x;   // over MROWS*DI
    const int d = idx & (DI - 1);
    const int m = idx >> 11;          // b*L + l
    const int l = m & (LSEQ - 1);

    float acc = cb[d];
#pragma unroll
    for (int j = 0; j < 4; j++) {
        const int ll = l - 3 + j;
        if (ll >= 0)
            acc = fmaf(cw[d * 4 + j], g_xz[(size_t)(m - 3 + j) * E2 + d], acc);
    }
    const float sg = 1.f / (1.f + __expf(-acc));
    g_xc[idx] = acc * sg;
}

// ---------------------------------------------------------------
// Selective scan. One thread per (b, d, s). 256 threads = 16 d x 16 s.
// Fused epilogue: y = (scan + D*u) * silu(z)
// ---------------------------------------------------------------
__global__ void __launch_bounds__(256) scan_k(
    const float* __restrict__ A_log, const float* __restrict__ Dp)
{
    const int s  = threadIdx.x & 15;
    const int dl = threadIdx.x >> 4;
    const int d  = blockIdx.x * 16 + dl;
    const int b  = blockIdx.y;

    const float As = -__expf(A_log[d * DS + s]);
    const float Dd = Dp[d];

    const float* dt_p = g_dt   + (size_t)b * LSEQ * DI + d;
    const float* u_p  = g_xc   + (size_t)b * LSEQ * DI + d;
    const float* bc_p = g_xdbl + (size_t)b * LSEQ * NX;
    const float* z_p  = g_xz   + (size_t)b * LSEQ * E2 + DI + d;
    float*       y_p  = g_yact + (size_t)b * LSEQ * DI + d;

    float h = 0.f;
    for (int l = 0; l < LSEQ; l++) {
        const float dt = __ldg(dt_p + (size_t)l * DI);
        const float u  = __ldg(u_p  + (size_t)l * DI);
        const float Bv = __ldg(bc_p + l * NX + DTR + s);
        const float Cv = __ldg(bc_p + l * NX + DTR + DS + s);

        const float dA = __expf(dt * As);
        h = fmaf(dA, h, dt * u * Bv);

        float y = h * Cv;
        y += __shfl_xor_sync(0xffffffffu, y, 8);
        y += __shfl_xor_sync(0xffffffffu, y, 4);
        y += __shfl_xor_sync(0xffffffffu, y, 2);
        y += __shfl_xor_sync(0xffffffffu, y, 1);

        if (s == 0) {
            const float zv = __ldg(z_p + (size_t)l * E2);
            const float sg = 1.f / (1.f + __expf(-zv));
            y_p[(size_t)l * DI] = (y + Dd * u) * (zv * sg);
        }
    }
}

// ---------------------------------------------------------------
// Residual add + LayerNorm. One block per row of 1024.
// ---------------------------------------------------------------
__global__ void __launch_bounds__(256) ln_k(
    const float* __restrict__ x,
    const float* __restrict__ g, const float* __restrict__ bb,
    float* __restrict__ out)
{
    const int r = blockIdx.x;
    const float* yp = g_yout + (size_t)r * DM;
    const float* xp = x      + (size_t)r * DM;

    float v[4];
    float sum = 0.f, sq = 0.f;
#pragma unroll
    for (int k = 0; k < 4; k++) {
        const int c = threadIdx.x + k * 256;
        const float t = yp[c] + xp[c];
        v[k] = t; sum += t; sq += t * t;
    }

    __shared__ float ssum[8], ssq[8];
#pragma unroll
    for (int o = 16; o; o >>= 1) {
        sum += __shfl_xor_sync(0xffffffffu, sum, o);
        sq  += __shfl_xor_sync(0xffffffffu, sq,  o);
    }
    const int w = threadIdx.x >> 5;
    if ((threadIdx.x & 31) == 0) { ssum[w] = sum; ssq[w] = sq; }
    __syncthreads();

    float ts = 0.f, tq = 0.f;
#pragma unroll
    for (int i = 0; i < 8; i++) { ts += ssum[i]; tq += ssq[i]; }

    const float mu  = ts * (1.f / DM);
    const float var = tq * (1.f / DM) - mu * mu;
    const float inv = rsqrtf(var + 1e-5f);

#pragma unroll
    for (int k = 0; k < 4; k++) {
        const int c = threadIdx.x + k * 256;
        out[(size_t)r * DM + c] = (v[k] - mu) * inv * g[c] + bb[c];
    }
}

// ---------------------------------------------------------------
extern "C" void kernel_launch(void* const* d_in, const int* in_sizes, int n_in,
                              void* d_out, int out_size)
{
    const float* x          = (const float*)d_in[0];
    const float* in_proj_w  = (const float*)d_in[1];
    const float* conv_w     = (const float*)d_in[2];
    const float* conv_b     = (const float*)d_in[3];
    const float* x_proj_w   = (const float*)d_in[4];
    const float* dt_proj_w  = (const float*)d_in[5];
    const float* dt_proj_b  = (const float*)d_in[6];
    const float* A_log      = (const float*)d_in[7];
    const float* Dp         = (const float*)d_in[8];
    const float* out_proj_w = (const float*)d_in[9];
    const float* ln_g       = (const float*)d_in[10];
    const float* ln_b       = (const float*)d_in[11];
    float* out = (float*)d_out;

    float *xz, *xc, *xdbl, *dt, *yact, *yout;
    cudaGetSymbolAddress((void**)&xz,   g_xz);
    cudaGetSymbolAddress((void**)&xc,   g_xc);
    cudaGetSymbolAddress((void**)&xdbl, g_xdbl);
    cudaGetSymbolAddress((void**)&dt,   g_dt);
    cudaGetSymbolAddress((void**)&yact, g_yact);
    cudaGetSymbolAddress((void**)&yout, g_yout);

    // 1) xz = x @ in_proj_w^T       (4096 x 4096 x 1024)
    sgemm_abt<0><<<dim3(E2 / 64, MROWS / 64), 256>>>(
        x, DM, in_proj_w, DM, xz, E2, E2, DM, nullptr);

    // 2) xc = silu(causal_conv(xi) + conv_b)
    conv_silu_k<<<(MROWS * DI) / 256, 256>>>(conv_w, conv_b);

    // 3) x_dbl = xc @ x_proj_w^T    (4096 x 96 x 2048)
    sgemm_abt<0><<<dim3((NX + 63) / 64, MROWS / 64), 256>>>(
        xc, DI, x_proj_w, DI, xdbl, NX, NX, DI, nullptr);

    // 4) dt = softplus(dt_r @ dt_proj_w^T + b)  (4096 x 2048 x 64)
    sgemm_abt<1><<<dim3(DI / 64, MROWS / 64), 256>>>(
        xdbl, NX, dt_proj_w, DTR, dt, DI, DI, DTR, dt_proj_b);

    // 5) selective scan + gating
    scan_k<<<dim3(DI / 16, BSZ), 256>>>(A_log, Dp);

    // 6) yout = yact @ out_proj_w^T (4096 x 1024 x 2048)
    sgemm_abt<0><<<dim3(DM / 64, MROWS / 64), 256>>>(
        yact, DI, out_proj_w, DI, yout, DM, DM, DI, nullptr);

    // 7) out = layernorm(yout + x)
    ln_k<<<MROWS, 256>>>(x, ln_g, ln_b, out);
}

// round 13
// speedup vs baseline: 1.5482x; 1.5437x over previous
#include <cuda_runtime.h>
#include <math.h>

// Problem constants (fixed by setup_inputs)
#define BSZ   2
#define LSEQ  2048
#define DM    1024
#define DI    2048          // d_inner
#define DS    16            // d_state
#define DTR   64            // dt_rank
#define NX    96            // dt_rank + 2*d_state
#define MROWS (BSZ*LSEQ)    // 4096
#define E2    (2*DI)        // 4096
#define NCH   16            // scan chunks
#define CL    (LSEQ/NCH)    // 128 steps per chunk

// -------- scratch (device globals; no allocation allowed) --------
__device__ float g_xz  [(size_t)MROWS * E2];   // in_proj output (xi | z)
__device__ float g_xc  [(size_t)MROWS * DI];   // conv+silu output
__device__ float g_xdbl[(size_t)MROWS * NX];   // x_proj output (dt_r | B | C)
__device__ float g_dt  [(size_t)MROWS * DI];   // softplus(dt)
__device__ float g_yact[(size_t)MROWS * DI];   // scan out * silu(z)
__device__ float g_yout[(size_t)MROWS * DM];   // out_proj output
__device__ float g_ca  [(size_t)BSZ * DI * DS * NCH];  // chunk prod(dA)
__device__ float g_cb  [(size_t)BSZ * DI * DS * NCH];  // chunk scan from h=0
__device__ float g_h0  [(size_t)BSZ * DI * DS * NCH];  // chunk entry state

// ---------------------------------------------------------------
// fp32 GEMM: C[M,N] = A[M,K] * B[N,K]^T (both K-major).
// 128x128 tile, 256 threads, 8x8 micro-tile (4+4 split for
// conflict-free LDS.128), BK=8, double-buffered smem.
// M % 128 == 0 (always 4096). N, K arbitrary mult of 4 / 8.
// EPI==1: v = softplus(v + bias[n])
// ---------------------------------------------------------------
template<int EPI>
__global__ void __launch_bounds__(256) sgemm128(
    const float* __restrict__ A, int lda,
    const float* __restrict__ Bm, int ldb,
    float* __restrict__ C, int ldc,
    int N, int K, const float* __restrict__ bias)
{
    __shared__ float As[2][8][128];
    __shared__ float Bs[2][8][128];

    const int tid = threadIdx.x;
    const int m0  = blockIdx.y * 128;
    const int n0  = blockIdx.x * 128;

    // global-load mapping: 2 threads per row, one float4 each
    const int lr = tid >> 1;          // 0..127
    const int lk = (tid & 1) * 4;     // 0 or 4

    // compute mapping: 16x16 thread grid, 4+4 split fragments
    const int tm = (tid >> 4) * 4;    // rows tm..tm+3, tm+64..tm+67
    const int tn = (tid & 15) * 4;    // cols tn..tn+3, tn+64..tn+67

    const float* Aload = A  + (size_t)(m0 + lr) * lda + lk;
    const float* Bload = Bm + (size_t)(n0 + lr) * ldb + lk;
    const bool   bval  = (n0 + lr) < N;

    float acc[8][8];
#pragma unroll
    for (int i = 0; i < 8; i++)
#pragma unroll
        for (int j = 0; j < 8; j++) acc[i][j] = 0.f;

    // preload tile 0
    float4 av = *reinterpret_cast<const float4*>(Aload);
    float4 bv = bval ? *reinterpret_cast<const float4*>(Bload)
                     : make_float4(0.f, 0.f, 0.f, 0.f);
    int buf = 0;
    As[0][lk+0][lr] = av.x; As[0][lk+1][lr] = av.y;
    As[0][lk+2][lr] = av.z; As[0][lk+3][lr] = av.w;
    Bs[0][lk+0][lr] = bv.x; Bs[0][lk+1][lr] = bv.y;
    Bs[0][lk+2][lr] = bv.z; Bs[0][lk+3][lr] = bv.w;
    __syncthreads();

    for (int k0 = 0; k0 < K; k0 += 8) {
        const bool more = (k0 + 8) < K;
        if (more) {
            av = *reinterpret_cast<const float4*>(Aload + k0 + 8);
            bv = bval ? *reinterpret_cast<const float4*>(Bload + k0 + 8)
                      : make_float4(0.f, 0.f, 0.f, 0.f);
        }
#pragma unroll
        for (int k = 0; k < 8; k++) {
            float4 a0 = *reinterpret_cast<const float4*>(&As[buf][k][tm]);
            float4 a1 = *reinterpret_cast<const float4*>(&As[buf][k][tm + 64]);
            float4 b0 = *reinterpret_cast<const float4*>(&Bs[buf][k][tn]);
            float4 b1 = *reinterpret_cast<const float4*>(&Bs[buf][k][tn + 64]);
            float a[8] = {a0.x, a0.y, a0.z, a0.w, a1.x, a1.y, a1.z, a1.w};
            float b[8] = {b0.x, b0.y, b0.z, b0.w, b1.x, b1.y, b1.z, b1.w};
#pragma unroll
            for (int i = 0; i < 8; i++)
#pragma unroll
                for (int j = 0; j < 8; j++)
                    acc[i][j] = fmaf(a[i], b[j], acc[i][j]);
        }
        if (more) {
            buf ^= 1;
            As[buf][lk+0][lr] = av.x; As[buf][lk+1][lr] = av.y;
            As[buf][lk+2][lr] = av.z; As[buf][lk+3][lr] = av.w;
            Bs[buf][lk+0][lr] = bv.x; Bs[buf][lk+1][lr] = bv.y;
            Bs[buf][lk+2][lr] = bv.z; Bs[buf][lk+3][lr] = bv.w;
            __syncthreads();
        }
    }

    // epilogue
#pragma unroll
    for (int i = 0; i < 8; i++) {
        const int m = m0 + tm + (i & 3) + (i >> 2) * 64;
#pragma unroll
        for (int jh = 0; jh < 2; jh++) {
            const int n = n0 + tn + jh * 64;
            if (n < N) {
                float4 v;
                float* vp = &v.x;
#pragma unroll
                for (int j = 0; j < 4; j++) {
                    float t = acc[i][jh * 4 + j];
                    if (EPI == 1) {
                        t += bias[n + j];
                        t = (t > 20.f) ? t : log1pf(__expf(t));
                    }
                    vp[j] = t;
                }
                *reinterpret_cast<float4*>(C + (size_t)m * ldc + n) = v;
            }
        }
    }
}

// ---------------------------------------------------------------
// Causal depthwise conv (width 4) + bias + SiLU on xi half of xz
// ---------------------------------------------------------------
__global__ void __launch_bounds__(256) conv_silu_k(
    const float* __restrict__ cw, const float* __restrict__ cb)
{
    const int idx = blockIdx.x * 256 + threadIdx.x;   // over MROWS*DI
    const int d = idx & (DI - 1);
    const int m = idx >> 11;          // b*L + l
    const int l = m & (LSEQ - 1);

    float acc = cb[d];
#pragma unroll
    for (int j = 0; j < 4; j++) {
        const int ll = l - 3 + j;
        if (ll >= 0)
            acc = fmaf(cw[d * 4 + j], g_xz[(size_t)(m - 3 + j) * E2 + d], acc);
    }
    const float sg = 1.f / (1.f + __expf(-acc));
    g_xc[idx] = acc * sg;
}

// ---------------------------------------------------------------
// Selective scan, chunked parallel form (3 passes).
// h_l = dA_l * h_{l-1} + dt_l*u_l*B_l  is a linear recurrence:
// pass1: per-chunk (a = prod dA, b = scan from 0)
// pass2: combine chunk summaries -> h at chunk starts
// pass3: re-scan each chunk from its true h0, emit gated y
// ---------------------------------------------------------------
__global__ void __launch_bounds__(256) scan_pass1(
    const float* __restrict__ A_log)
{
    const int s  = threadIdx.x & 15;
    const int dl = threadIdx.x >> 4;
    const int d  = blockIdx.x * 16 + dl;
    const int c  = blockIdx.y;
    const int b  = blockIdx.z;

    const float As = -__expf(A_log[d * DS + s]);
    const float* dt_p = g_dt   + (size_t)b * LSEQ * DI + d;
    const float* u_p  = g_xc   + (size_t)b * LSEQ * DI + d;
    const float* bc_p = g_xdbl + (size_t)b * LSEQ * NX;

    float a = 1.f, h = 0.f;
    const int l0 = c * CL;
#pragma unroll 4
    for (int l = l0; l < l0 + CL; l++) {
        const float dt = __ldg(dt_p + (size_t)l * DI);
        const float u  = __ldg(u_p  + (size_t)l * DI);
        const float Bv = __ldg(bc_p + l * NX + DTR + s);
        const float dA = __expf(dt * As);
        a *= dA;
        h = fmaf(dA, h, dt * u * Bv);
    }
    const size_t idx = (((size_t)b * DI + d) * DS + s) * NCH + c;
    g_ca[idx] = a;
    g_cb[idx] = h;
}

__global__ void __launch_bounds__(256) scan_pass2()
{
    const size_t t = (size_t)blockIdx.x * 256 + threadIdx.x; // BSZ*DI*DS
    const size_t base = t * NCH;
    float h = 0.f;
#pragma unroll
    for (int c = 0; c < NCH; c++) {
        g_h0[base + c] = h;
        h = fmaf(g_ca[base + c], h, g_cb[base + c]);
    }
}

__global__ void __launch_bounds__(256) scan_pass3(
    const float* __restrict__ A_log, const float* __restrict__ Dp)
{
    const int s  = threadIdx.x & 15;
    const int dl = threadIdx.x >> 4;
    const int d  = blockIdx.x * 16 + dl;
    const int c  = blockIdx.y;
    const int b  = blockIdx.z;

    const float As = -__expf(A_log[d * DS + s]);
    const float Dd = Dp[d];

    const float* dt_p = g_dt   + (size_t)b * LSEQ * DI + d;
    const float* u_p  = g_xc   + (size_t)b * LSEQ * DI + d;
    const float* bc_p = g_xdbl + (size_t)b * LSEQ * NX;
    const float* z_p  = g_xz   + (size_t)b * LSEQ * E2 + DI + d;
    float*       y_p  = g_yact + (size_t)b * LSEQ * DI + d;

    float h = g_h0[(((size_t)b * DI + d) * DS + s) * NCH + c];
    const int l0 = c * CL;
#pragma unroll 2
    for (int l = l0; l < l0 + CL; l++) {
        const float dt = __ldg(dt_p + (size_t)l * DI);
        const float u  = __ldg(u_p  + (size_t)l * DI);
        const float Bv = __ldg(bc_p + l * NX + DTR + s);
        const float Cv = __ldg(bc_p + l * NX + DTR + DS + s);

        const float dA = __expf(dt * As);
        h = fmaf(dA, h, dt * u * Bv);

        float y = h * Cv;
        y += __shfl_xor_sync(0xffffffffu, y, 8);
        y += __shfl_xor_sync(0xffffffffu, y, 4);
        y += __shfl_xor_sync(0xffffffffu, y, 2);
        y += __shfl_xor_sync(0xffffffffu, y, 1);

        if (s == 0) {
            const float zv = __ldg(z_p + (size_t)l * E2);
            const float sg = 1.f / (1.f + __expf(-zv));
            y_p[(size_t)l * DI] = (y + Dd * u) * (zv * sg);
        }
    }
}

// ---------------------------------------------------------------
// Residual add + LayerNorm. One block per row of 1024.
// ---------------------------------------------------------------
__global__ void __launch_bounds__(256) ln_k(
    const float* __restrict__ x,
    const float* __restrict__ g, const float* __restrict__ bb,
    float* __restrict__ out)
{
    const int r = blockIdx.x;
    const float* yp = g_yout + (size_t)r * DM;
    const float* xp = x      + (size_t)r * DM;

    float v[4];
    float sum = 0.f, sq = 0.f;
#pragma unroll
    for (int k = 0; k < 4; k++) {
        const int c = threadIdx.x + k * 256;
        const float t = yp[c] + xp[c];
        v[k] = t; sum += t; sq += t * t;
    }

    __shared__ float ssum[8], ssq[8];
#pragma unroll
    for (int o = 16; o; o >>= 1) {
        sum += __shfl_xor_sync(0xffffffffu, sum, o);
        sq  += __shfl_xor_sync(0xffffffffu, sq,  o);
    }
    const int w = threadIdx.x >> 5;
    if ((threadIdx.x & 31) == 0) { ssum[w] = sum; ssq[w] = sq; }
    __syncthreads();

    float ts = 0.f, tq = 0.f;
#pragma unroll
    for (int i = 0; i < 8; i++) { ts += ssum[i]; tq += ssq[i]; }

    const float mu  = ts * (1.f / DM);
    const float var = tq * (1.f / DM) - mu * mu;
    const float inv = rsqrtf(var + 1e-5f);

#pragma unroll
    for (int k = 0; k < 4; k++) {
        const int c = threadIdx.x + k * 256;
        out[(size_t)r * DM + c] = (v[k] - mu) * inv * g[c] + bb[c];
    }
}

// ---------------------------------------------------------------
extern "C" void kernel_launch(void* const* d_in, const int* in_sizes, int n_in,
                              void* d_out, int out_size)
{
    const float* x          = (const float*)d_in[0];
    const float* in_proj_w  = (const float*)d_in[1];
    const float* conv_w     = (const float*)d_in[2];
    const float* conv_b     = (const float*)d_in[3];
    const float* x_proj_w   = (const float*)d_in[4];
    const float* dt_proj_w  = (const float*)d_in[5];
    const float* dt_proj_b  = (const float*)d_in[6];
    const float* A_log      = (const float*)d_in[7];
    const float* Dp         = (const float*)d_in[8];
    const float* out_proj_w = (const float*)d_in[9];
    const float* ln_g       = (const float*)d_in[10];
    const float* ln_b       = (const float*)d_in[11];
    float* out = (float*)d_out;

    float *xz, *xc, *xdbl, *dt, *yact, *yout;
    cudaGetSymbolAddress((void**)&xz,   g_xz);
    cudaGetSymbolAddress((void**)&xc,   g_xc);
    cudaGetSymbolAddress((void**)&xdbl, g_xdbl);
    cudaGetSymbolAddress((void**)&dt,   g_dt);
    cudaGetSymbolAddress((void**)&yact, g_yact);
    cudaGetSymbolAddress((void**)&yout, g_yout);

    // 1) xz = x @ in_proj_w^T       (4096 x 4096 x 1024)
    sgemm128<0><<<dim3(E2 / 128, MROWS / 128), 256>>>(
        x, DM, in_proj_w, DM, xz, E2, E2, DM, nullptr);

    // 2) xc = silu(causal_conv(xi) + conv_b)
    conv_silu_k<<<(MROWS * DI) / 256, 256>>>(conv_w, conv_b);

    // 3) x_dbl = xc @ x_proj_w^T    (4096 x 96 x 2048)
    sgemm128<0><<<dim3((NX + 127) / 128, MROWS / 128), 256>>>(
        xc, DI, x_proj_w, DI, xdbl, NX, NX, DI, nullptr);

    // 4) dt = softplus(dt_r @ dt_proj_w^T + b)  (4096 x 2048 x 64)
    sgemm128<1><<<dim3(DI / 128, MROWS / 128), 256>>>(
        xdbl, NX, dt_proj_w, DTR, dt, DI, DI, DTR, dt_proj_b);

    // 5) selective scan (chunked parallel) + gating
    scan_pass1<<<dim3(DI / 16, NCH, BSZ), 256>>>(A_log);
    scan_pass2<<<(BSZ * DI * DS) / 256, 256>>>();
    scan_pass3<<<dim3(DI / 16, NCH, BSZ), 256>>>(A_log, Dp);

    // 6) yout = yact @ out_proj_w^T (4096 x 1024 x 2048)
    sgemm128<0><<<dim3(DM / 128, MROWS / 128), 256>>>(
        yact, DI, out_proj_w, DI, yout, DM, DM, DI, nullptr);

    // 7) out = layernorm(yout + x)
    ln_k<<<MROWS, 256>>>(x, ln_g, ln_b, out);
}